// round 14
// baseline (speedup 1.0000x reference)
#include <cuda_runtime.h>

// Problem dims
#define B_  64
#define T_  2048
#define E_  256
#define A_  128
#define P_  128
#define R_  1024
#define D_  1024
#define H_  256
#define F_  32
#define KS_ 31
#define PAD_ 15

// ---------------- scratch (no allocations allowed) ----------------
__device__ float g_part[16 * B_ * 4096];      // GEMM partial slabs (shared a/d)
__device__ float g_pq_part[8 * B_ * A_];      // pq partials
__device__ float g_proj_part[8 * B_ * H_];    // proj partials
__device__ float g_ah[B_ * R_];
__device__ float g_ac[B_ * R_];
__device__ float g_energies[B_ * T_];
__device__ float g_ctx[B_ * E_];
__device__ float g_dh[B_ * D_];
__device__ float g_dc[B_ * D_];

// ---------------- helpers ----------------
__device__ __forceinline__ unsigned f2tf(float f) {
    unsigned u;
    asm("cvt.rna.tf32.f32 %0, %1;" : "=r"(u) : "f"(f));
    return u;
}

__device__ __forceinline__ void mma_tf32(float* c,
    unsigned a0, unsigned a1, unsigned a2, unsigned a3,
    unsigned b0, unsigned b1)
{
    asm volatile(
        "mma.sync.aligned.m16n8k8.row.col.f32.tf32.tf32.f32 "
        "{%0,%1,%2,%3}, {%4,%5,%6,%7}, {%8,%9}, {%0,%1,%2,%3};"
        : "+f"(c[0]), "+f"(c[1]), "+f"(c[2]), "+f"(c[3])
        : "r"(a0), "r"(a1), "r"(a2), "r"(a3), "r"(b0), "r"(b1));
}

__device__ __forceinline__ void cp16(void* smem_dst, const void* gsrc) {
    unsigned dst = (unsigned)__cvta_generic_to_shared(smem_dst);
    asm volatile("cp.async.ca.shared.global [%0], [%1], 16;"
                 :: "r"(dst), "l"(gsrc));
}
__device__ __forceinline__ void cp_commit() {
    asm volatile("cp.async.commit_group;");
}
__device__ __forceinline__ void cp_wait1() {
    asm volatile("cp.async.wait_group 1;");
}
__device__ __forceinline__ void cp_wait0() {
    asm volatile("cp.async.wait_group 0;");
}

__device__ __forceinline__ float sigm(float x) { return 1.f / (1.f + __expf(-x)); }
__device__ __forceinline__ float fast_tanh(float x) {
    float e = __expf(2.f * x);
    return 1.f - __fdividef(2.f, e + 1.f);
}

// ---------------- tf32 MMA 3-segment GEMM, split-K, partial-slab output ----------
// Slab y: Cpart[y*64*N + m*N + n] = partial sum over this block's k-range.
// Every (x,y) block writes its slab region (zeros if its k-range is empty).
__global__ __launch_bounds__(128) void mma_gemm3(
    const float* __restrict__ x1, const float* __restrict__ W1, int K1, int ld1,
    const float* __restrict__ x2, const float* __restrict__ W2, int K2, int ld2,
    const float* __restrict__ x3, const float* __restrict__ W3, int K3, int ld3,
    float* __restrict__ Cpart, int N)
{
    __shared__ float As[3][64][36];
    __shared__ float Ws[3][32][36];

    const int tid  = threadIdx.x;
    const int lane = tid & 31;
    const int w    = tid >> 5;
    const int gid  = lane >> 2;
    const int tig  = lane & 3;
    const int n0   = blockIdx.x * 32;

    const int S      = gridDim.y;
    const int nt_tot = (K1 + K2 + K3) >> 5;
    const int per    = (nt_tot + S - 1) / S;
    const int gt0    = blockIdx.y * per;
    const int gt1    = min(gt0 + per, nt_tot);

    float acc[4][4] = {};

    int base = 0;
#pragma unroll
    for (int s = 0; s < 3; s++) {
        const float* x  = (s == 0) ? x1 : (s == 1) ? x2 : x3;
        const float* W  = (s == 0) ? W1 : (s == 1) ? W2 : W3;
        const int K     = (s == 0) ? K1 : (s == 1) ? K2 : K3;
        const int ld    = (s == 0) ? ld1 : (s == 1) ? ld2 : ld3;
        if (K == 0) continue;
        const int nts = K >> 5;
        const int lo = max(gt0 - base, 0), hi = min(gt1 - base, nts);
        base += nts;
        if (lo >= hi) continue;

        __syncthreads();

        auto issue = [&](int tile, int buf) {
            int k0 = tile * 32;
#pragma unroll
            for (int r = 0; r < 4; r++) {
                int j = tid + r * 128;
                int m = j >> 3, kq = j & 7;
                cp16(&As[buf][m][kq * 4], x + (size_t)m * K + k0 + kq * 4);
            }
#pragma unroll
            for (int r = 0; r < 2; r++) {
                int j = tid + r * 128;
                int n = j >> 3, kq = j & 7;
                cp16(&Ws[buf][n][kq * 4], W + (size_t)(n0 + n) * ld + k0 + kq * 4);
            }
        };

        issue(lo, 0);
        cp_commit();
        if (hi - lo > 1) issue(lo + 1, 1);
        cp_commit();

        for (int it = lo; it < hi; it++) {
            cp_wait1();
            __syncthreads();
            int nx = it + 2;
            if (nx < hi) issue(nx, (nx - lo) % 3);
            cp_commit();

            const int buf = (it - lo) % 3;
#pragma unroll
            for (int kk = 0; kk < 32; kk += 8) {
                unsigned bb0 = f2tf(Ws[buf][w * 8 + gid][kk + tig]);
                unsigned bb1 = f2tf(Ws[buf][w * 8 + gid][kk + tig + 4]);
#pragma unroll
                for (int mt = 0; mt < 4; mt++) {
                    int ra = mt * 16 + gid;
                    unsigned a0 = f2tf(As[buf][ra][kk + tig]);
                    unsigned a1 = f2tf(As[buf][ra + 8][kk + tig]);
                    unsigned a2 = f2tf(As[buf][ra][kk + tig + 4]);
                    unsigned a3 = f2tf(As[buf][ra + 8][kk + tig + 4]);
                    mma_tf32(acc[mt], a0, a1, a2, a3, bb0, bb1);
                }
            }
        }
    }

    float* C = Cpart + (size_t)blockIdx.y * 64 * N;
    int n = n0 + w * 8 + tig * 2;
#pragma unroll
    for (int mt = 0; mt < 4; mt++) {
        int ra = mt * 16 + gid, rb = ra + 8;
        C[(size_t)ra * N + n]     = acc[mt][0];
        C[(size_t)ra * N + n + 1] = acc[mt][1];
        C[(size_t)rb * N + n]     = acc[mt][2];
        C[(size_t)rb * N + n + 1] = acc[mt][3];
    }
}

// ---------------- LSTM pointwise: sums S partial slabs + biases ----------------
__global__ __launch_bounds__(256) void lstm_pointwise(
    const float* __restrict__ parts, int S,
    const float* __restrict__ b_ih, const float* __restrict__ b_hh,
    const float* __restrict__ c_prev,
    float* __restrict__ h_out, float* __restrict__ c_out, int Nc)
{
    int idx4 = blockIdx.x * blockDim.x + threadIdx.x;
    if (idx4 >= (B_ * 1024) / 4) return;
    int q = Nc / 4;
    int b = idx4 / q, j4 = idx4 - b * q;

    const float4* bi = (const float4*)b_ih;
    const float4* bh = (const float4*)b_hh;
    float4 gi4, gf4, gg4, go4;
    {
        float4 x = bi[j4],         y = bh[j4];
        gi4 = make_float4(x.x + y.x, x.y + y.y, x.z + y.z, x.w + y.w);
        x = bi[q + j4];            y = bh[q + j4];
        gf4 = make_float4(x.x + y.x, x.y + y.y, x.z + y.z, x.w + y.w);
        x = bi[2 * q + j4];        y = bh[2 * q + j4];
        gg4 = make_float4(x.x + y.x, x.y + y.y, x.z + y.z, x.w + y.w);
        x = bi[3 * q + j4];        y = bh[3 * q + j4];
        go4 = make_float4(x.x + y.x, x.y + y.y, x.z + y.z, x.w + y.w);
    }
    for (int s = 0; s < S; s++) {
        const float4* p = (const float4*)(parts + (size_t)s * B_ * 4 * Nc
                                          + (size_t)b * 4 * Nc);
        float4 v;
        v = p[j4];         gi4.x += v.x; gi4.y += v.y; gi4.z += v.z; gi4.w += v.w;
        v = p[q + j4];     gf4.x += v.x; gf4.y += v.y; gf4.z += v.z; gf4.w += v.w;
        v = p[2 * q + j4]; gg4.x += v.x; gg4.y += v.y; gg4.z += v.z; gg4.w += v.w;
        v = p[3 * q + j4]; go4.x += v.x; go4.y += v.y; go4.z += v.z; go4.w += v.w;
    }
    float4 cp4 = ((const float4*)c_prev)[idx4];
    float4 h4, c4;
    { float c2 = sigm(gf4.x) * cp4.x + sigm(gi4.x) * fast_tanh(gg4.x);
      h4.x = sigm(go4.x) * fast_tanh(c2); c4.x = c2; }
    { float c2 = sigm(gf4.y) * cp4.y + sigm(gi4.y) * fast_tanh(gg4.y);
      h4.y = sigm(go4.y) * fast_tanh(c2); c4.y = c2; }
    { float c2 = sigm(gf4.z) * cp4.z + sigm(gi4.z) * fast_tanh(gg4.z);
      h4.z = sigm(go4.z) * fast_tanh(c2); c4.z = c2; }
    { float c2 = sigm(gf4.w) * cp4.w + sigm(gi4.w) * fast_tanh(gg4.w);
      h4.w = sigm(go4.w) * fast_tanh(c2); c4.w = c2; }
    ((float4*)h_out)[idx4] = h4;
    ((float4*)c_out)[idx4] = c4;
}

// ---------------- fused conv31 + MMA location-fc + in-fragment energy ----------
// grid (T/64, B), 128 threads, dynamic smem (~72 KB).
// smem float offsets:
//   s_pm   0      [64][132]
//   s_lfc  8448   [128][36]
//   s_cv   13056  [64][36]
//   s_w    15360  [1984]
//   s_aw   17344  [2*94] (192 reserved)
//   s_pq   17536  [128]
//   s_wv   17664  [128]
//   s_part 17792  [4][64]
#define ENERGY_SMEM_FLOATS 18048
__global__ __launch_bounds__(128) void energy_kernel(
    const float* __restrict__ att_w, const float* __restrict__ att_w_cum,
    const float* __restrict__ pm,        // [B,T,A]
    const float* __restrict__ pq_part,   // [8][B][A]
    const float* __restrict__ W_loc,     // [F,2,31]
    const float* __restrict__ W_lfc,     // [A,F]
    const float* __restrict__ W_v,       // [A]
    float* __restrict__ energies)        // [B,T]
{
    extern __shared__ float sm[];
    float* s_pm   = sm;
    float* s_lfc  = sm + 8448;
    float* s_cv   = sm + 13056;
    float* s_w    = sm + 15360;
    float* s_aw   = sm + 17344;
    float* s_pq   = sm + 17536;
    float* s_wv   = sm + 17664;
    float* s_part = sm + 17792;

    const int b   = blockIdx.y;
    const int t0  = blockIdx.x * 64;
    const int tid = threadIdx.x;
    const int lane = tid & 31, w = tid >> 5;
    const int gid = lane >> 2, tig = lane & 3;

    // cp.async prefetch: pm tile, lfc, wv
    const float* pmrow = pm + ((size_t)b * T_ + t0) * A_;
#pragma unroll
    for (int r = 0; r < 16; r++) {
        int idx = tid + r * 128;
        int row = idx >> 5, q = idx & 31;
        cp16(s_pm + row * 132 + q * 4, pmrow + row * 128 + q * 4);
    }
#pragma unroll
    for (int r = 0; r < 8; r++) {
        int idx = tid + r * 128;
        int row = idx >> 3, q = idx & 7;
        cp16(s_lfc + row * 36 + q * 4, W_lfc + row * 32 + q * 4);
    }
    if (tid < 32) cp16(s_wv + tid * 4, W_v + tid * 4);
    cp_commit();

    // halo + conv weights + pq slab sum (plain loads)
    for (int i = tid; i < 94; i += 128) {
        int g = t0 - PAD_ + i;
        bool ok = (g >= 0) && (g < T_);
        s_aw[i]      = ok ? att_w[b * T_ + g] : 0.f;
        s_aw[94 + i] = ok ? att_w_cum[b * T_ + g] : 0.f;
    }
    for (int i = tid; i < F_ * 2 * KS_; i += 128) s_w[i] = W_loc[i];
    {
        float v = 0.f;
#pragma unroll
        for (int s = 0; s < 8; s++) v += pq_part[s * (B_ * A_) + b * A_ + tid];
        s_pq[tid] = v;
    }
    __syncthreads();

    // phase 1: conv -> s_cv[t][f]
    {
        int f = tid & 31, tg = tid >> 5;
        float acc[16];
#pragma unroll
        for (int i = 0; i < 16; i++) acc[i] = 0.f;
#pragma unroll
        for (int c = 0; c < 2; c++) {
            float av[46];
#pragma unroll
            for (int i = 0; i < 46; i++) av[i] = s_aw[c * 94 + tg * 16 + i];
#pragma unroll
            for (int k = 0; k < KS_; k++) {
                float wv = s_w[(f * 2 + c) * KS_ + k];
#pragma unroll
                for (int tt = 0; tt < 16; tt++) acc[tt] += wv * av[k + tt];
            }
        }
#pragma unroll
        for (int tt = 0; tt < 16; tt++) s_cv[(tg * 16 + tt) * 36 + f] = acc[tt];
    }
    cp_wait0();
    __syncthreads();

    // phase 2: MMA la = cv @ lfc^T, tanh-reduce in fragment layout
    {
        float acc[4][4][4] = {};
#pragma unroll
        for (int kk = 0; kk < 32; kk += 8) {
            unsigned af[4][4];
#pragma unroll
            for (int mt = 0; mt < 4; mt++) {
                int ra = mt * 16 + gid;
                af[mt][0] = f2tf(s_cv[ra * 36 + kk + tig]);
                af[mt][1] = f2tf(s_cv[(ra + 8) * 36 + kk + tig]);
                af[mt][2] = f2tf(s_cv[ra * 36 + kk + tig + 4]);
                af[mt][3] = f2tf(s_cv[(ra + 8) * 36 + kk + tig + 4]);
            }
#pragma unroll
            for (int nt = 0; nt < 4; nt++) {
                int n = w * 32 + nt * 8 + gid;
                unsigned bb0 = f2tf(s_lfc[n * 36 + kk + tig]);
                unsigned bb1 = f2tf(s_lfc[n * 36 + kk + tig + 4]);
#pragma unroll
                for (int mt = 0; mt < 4; mt++)
                    mma_tf32(acc[mt][nt], af[mt][0], af[mt][1], af[mt][2], af[mt][3],
                             bb0, bb1);
            }
        }
        // per-thread tanh + W_v dot over owned fragment elements
        float part[8];
#pragma unroll
        for (int i = 0; i < 8; i++) part[i] = 0.f;
#pragma unroll
        for (int nt = 0; nt < 4; nt++) {
            int a0 = w * 32 + nt * 8 + tig * 2, a1 = a0 + 1;
            float pq0 = s_pq[a0], pq1 = s_pq[a1];
            float wv0 = s_wv[a0], wv1 = s_wv[a1];
#pragma unroll
            for (int mt = 0; mt < 4; mt++) {
                int tr0 = mt * 16 + gid, tr1 = tr0 + 8;
                part[mt * 2] +=
                    fast_tanh(pq0 + s_pm[tr0 * 132 + a0] + acc[mt][nt][0]) * wv0
                  + fast_tanh(pq1 + s_pm[tr0 * 132 + a1] + acc[mt][nt][1]) * wv1;
                part[mt * 2 + 1] +=
                    fast_tanh(pq0 + s_pm[tr1 * 132 + a0] + acc[mt][nt][2]) * wv0
                  + fast_tanh(pq1 + s_pm[tr1 * 132 + a1] + acc[mt][nt][3]) * wv1;
            }
        }
        // reduce over tig (lanes xor 1, xor 2)
#pragma unroll
        for (int i = 0; i < 8; i++) {
            part[i] += __shfl_xor_sync(0xffffffffu, part[i], 1);
            part[i] += __shfl_xor_sync(0xffffffffu, part[i], 2);
        }
        if (tig == 0) {
#pragma unroll
            for (int mt = 0; mt < 4; mt++) {
                s_part[w * 64 + mt * 16 + gid]     = part[mt * 2];
                s_part[w * 64 + mt * 16 + gid + 8] = part[mt * 2 + 1];
            }
        }
    }
    __syncthreads();
    if (tid < 64)
        energies[b * T_ + t0 + tid] = s_part[tid] + s_part[64 + tid]
                                    + s_part[128 + tid] + s_part[192 + tid];
}

// ---------------- fused masked softmax + context ----------------
// grid B_, 512 threads. Softmax over T (mask int32), weights -> d_out + smem,
// then ctx[b,:] computed in-block (plain store).
__global__ __launch_bounds__(512) void softmax_ctx_kernel(
    const float* __restrict__ energies, const int* __restrict__ mask,
    const float* __restrict__ memory,
    float* __restrict__ weights, float* __restrict__ ctx)
{
    __shared__ float s_wt[T_];
    __shared__ float s_red[8 * 64 * 4];
    __shared__ float red[16];
    __shared__ float s_bcast;

    int b = blockIdx.x, tid = threadIdx.x;
    int lane = tid & 31, wid = tid >> 5;

    float v[4];
    float mx = -3.4e38f;
#pragma unroll
    for (int r = 0; r < 4; r++) {
        int t = tid + r * 512;
        float e = energies[b * T_ + t];
        if (mask[b * T_ + t] != 0) e = -1e30f;
        v[r] = e;
        mx = fmaxf(mx, e);
    }
#pragma unroll
    for (int o = 16; o; o >>= 1) mx = fmaxf(mx, __shfl_xor_sync(0xffffffffu, mx, o));
    if (lane == 0) red[wid] = mx;
    __syncthreads();
    if (tid < 16) {
        float m = red[tid];
#pragma unroll
        for (int o = 8; o; o >>= 1) m = fmaxf(m, __shfl_xor_sync(0xffffu, m, o));
        if (tid == 0) s_bcast = m;
    }
    __syncthreads();
    mx = s_bcast;
    float sum = 0.f;
#pragma unroll
    for (int r = 0; r < 4; r++) { v[r] = __expf(v[r] - mx); sum += v[r]; }
#pragma unroll
    for (int o = 16; o; o >>= 1) sum += __shfl_xor_sync(0xffffffffu, sum, o);
    if (lane == 0) red[wid] = sum;
    __syncthreads();
    if (tid < 16) {
        float m = red[tid];
#pragma unroll
        for (int o = 8; o; o >>= 1) m += __shfl_xor_sync(0xffffu, m, o);
        if (tid == 0) s_bcast = m;
    }
    __syncthreads();
    float inv = 1.f / s_bcast;
#pragma unroll
    for (int r = 0; r < 4; r++) {
        int t = tid + r * 512;
        float wv = v[r] * inv;
        weights[b * T_ + t] = wv;
        s_wt[t] = wv;
    }
    __syncthreads();

    // ctx: thread = (c4 = tid&63, trow = tid>>6); t stride 8
    {
        int c4 = tid & 63, trow = tid >> 6;
        const float4* mb = (const float4*)(memory + (size_t)b * T_ * E_);
        float4 acc = make_float4(0.f, 0.f, 0.f, 0.f);
#pragma unroll 8
        for (int t = trow; t < T_; t += 8) {
            float wv = s_wt[t];
            float4 m = mb[t * 64 + c4];
            acc.x += wv * m.x; acc.y += wv * m.y;
            acc.z += wv * m.z; acc.w += wv * m.w;
        }
        ((float4*)s_red)[trow * 64 + c4] = acc;
    }
    __syncthreads();
    if (tid < 64) {
        float4 a = make_float4(0.f, 0.f, 0.f, 0.f);
#pragma unroll
        for (int r = 0; r < 8; r++) {
            float4 p = ((float4*)s_red)[r * 64 + tid];
            a.x += p.x; a.y += p.y; a.z += p.z; a.w += p.w;
        }
        ((float4*)ctx)[b * 64 + tid] = a;
    }
}

// ---------------- proj finalize + stop gate ----------------
// grid B_, 256 threads. out_proj[r,:] = sum slabs + bias; out_stop[r] = gate.
__global__ __launch_bounds__(256) void proj_fin_gate_kernel(
    const float* __restrict__ proj_part, const float* __restrict__ b_proj,
    const float* __restrict__ dh, const float* __restrict__ ctx,
    const float* __restrict__ W_gate, const float* __restrict__ b_gate,
    float* __restrict__ out_proj, float* __restrict__ out_stop)
{
    __shared__ float red[8];
    int r = blockIdx.x, tid = threadIdx.x;
    int lane = tid & 31, wid = tid >> 5;

    float v = b_proj[tid];
#pragma unroll
    for (int s = 0; s < 8; s++) v += proj_part[s * (B_ * H_) + r * H_ + tid];
    out_proj[r * H_ + tid] = v;

    float acc = 0.f;
    const float* xr = dh + (size_t)r * D_;
#pragma unroll 4
    for (int k = tid; k < D_; k += 256) acc += xr[k] * W_gate[k];
    acc += ctx[r * E_ + tid] * W_gate[D_ + tid];
#pragma unroll
    for (int o = 16; o; o >>= 1) acc += __shfl_xor_sync(0xffffffffu, acc, o);
    if (lane == 0) red[wid] = acc;
    __syncthreads();
    if (tid < 8) {
        float m = red[tid];
#pragma unroll
        for (int o = 4; o; o >>= 1) m += __shfl_xor_sync(0xffu, m, o);
        if (tid == 0) out_stop[r] = m + b_gate[0];
    }
}

// ---------------- launch ----------------
extern "C" void kernel_launch(void* const* d_in, const int* in_sizes, int n_in,
                              void* d_out, int out_size)
{
    const float* last_frame = (const float*)d_in[0];
    const float* att_h      = (const float*)d_in[1];
    const float* att_c      = (const float*)d_in[2];
    const float* att_w      = (const float*)d_in[3];
    const float* att_w_cum  = (const float*)d_in[4];
    const float* att_ctx    = (const float*)d_in[5];
    const float* dec_h      = (const float*)d_in[6];
    const float* dec_c      = (const float*)d_in[7];
    const float* memory     = (const float*)d_in[8];
    const float* pmem       = (const float*)d_in[9];
    const float* W_ih_a     = (const float*)d_in[10];
    const float* W_hh_a     = (const float*)d_in[11];
    const float* b_ih_a     = (const float*)d_in[12];
    const float* b_hh_a     = (const float*)d_in[13];
    const float* W_q        = (const float*)d_in[14];
    const float* W_v        = (const float*)d_in[15];
    const float* W_loc      = (const float*)d_in[16];
    const float* W_lfc      = (const float*)d_in[17];
    const float* W_ih_d     = (const float*)d_in[18];
    const float* W_hh_d     = (const float*)d_in[19];
    const float* b_ih_d     = (const float*)d_in[20];
    const float* b_hh_d     = (const float*)d_in[21];
    const float* W_proj     = (const float*)d_in[22];
    const float* b_proj     = (const float*)d_in[23];
    const float* W_gate     = (const float*)d_in[24];
    const float* b_gate     = (const float*)d_in[25];
    const int*   mask       = (const int*)d_in[26];

    float* out = (float*)d_out;
    float* out_proj = out;                      // [64,256]
    float* out_stop = out + B_ * H_;            // [64,1]
    float* out_w    = out + B_ * H_ + B_;       // [64,2048]

    float *part, *pq_part, *proj_part, *ah, *ac, *energies, *ctx, *dh, *dc;
    cudaGetSymbolAddress((void**)&part,      g_part);
    cudaGetSymbolAddress((void**)&pq_part,   g_pq_part);
    cudaGetSymbolAddress((void**)&proj_part, g_proj_part);
    cudaGetSymbolAddress((void**)&ah,        g_ah);
    cudaGetSymbolAddress((void**)&ac,        g_ac);
    cudaGetSymbolAddress((void**)&energies,  g_energies);
    cudaGetSymbolAddress((void**)&ctx,       g_ctx);
    cudaGetSymbolAddress((void**)&dh,        g_dh);
    cudaGetSymbolAddress((void**)&dc,        g_dc);

    const int energy_smem = ENERGY_SMEM_FLOATS * 4;   // 72,192 B
    cudaFuncSetAttribute(energy_kernel,
                         cudaFuncAttributeMaxDynamicSharedMemorySize, energy_smem);

    // 1) attention LSTM gates -> partial slabs (S=8)
    mma_gemm3<<<dim3(128, 8), 128>>>(last_frame, W_ih_a,       P_, P_ + E_,
                                     att_ctx,    W_ih_a + P_,  E_, P_ + E_,
                                     att_h,      W_hh_a,       R_, R_,
                                     part, 4 * R_);
    // 2) attention LSTM cell (sums 8 slabs + biases)
    lstm_pointwise<<<(B_ * 1024) / 1024, 256>>>(part, 8, b_ih_a, b_hh_a,
                                                att_c, ah, ac, R_);
    // 3) pq partials (S=8)
    mma_gemm3<<<dim3(A_ / 32, 8), 128>>>(ah, W_q, R_, R_,
                                         nullptr, nullptr, 0, 0,
                                         nullptr, nullptr, 0, 0,
                                         pq_part, A_);
    // 4) fused conv + MMA-la + energies (sums pq slabs in-kernel)
    energy_kernel<<<dim3(T_ / 64, B_), 128, energy_smem>>>(
        att_w, att_w_cum, pmem, pq_part, W_loc, W_lfc, W_v, energies);
    // 5) fused softmax + ctx
    softmax_ctx_kernel<<<B_, 512>>>(energies, mask, memory, out_w, ctx);
    // 6) decoder LSTM gates -> partial slabs (S=16)
    mma_gemm3<<<dim3(128, 16), 128>>>(ah,    W_ih_d,       R_, R_ + E_,
                                      ctx,   W_ih_d + R_,  E_, R_ + E_,
                                      dec_h, W_hh_d,       D_, D_,
                                      part, 4 * D_);
    // 7) decoder LSTM cell (sums 16 slabs + biases)
    lstm_pointwise<<<(B_ * 1024) / 1024, 256>>>(part, 16, b_ih_d, b_hh_d,
                                                dec_c, dh, dc, D_);
    // 8) proj partials (S=8)
    mma_gemm3<<<dim3(H_ / 32, 8), 128>>>(dh,  W_proj,       D_, D_ + E_,
                                         ctx, W_proj + D_,  E_, D_ + E_,
                                         nullptr, nullptr, 0, 0,
                                         proj_part, H_);
    // 9) proj finalize + stop gate
    proj_fin_gate_kernel<<<B_, 256>>>(proj_part, b_proj, dh, ctx,
                                      W_gate, b_gate, out_proj, out_stop);
}

// round 15
// speedup vs baseline: 1.5319x; 1.5319x over previous
#include <cuda_runtime.h>

// Problem dims
#define B_  64
#define T_  2048
#define E_  256
#define A_  128
#define P_  128
#define R_  1024
#define D_  1024
#define H_  256
#define F_  32
#define KS_ 31
#define PAD_ 15

// ---------------- scratch (no allocations allowed) ----------------
__device__ float g_gates_a[B_ * 4096];
__device__ float g_gates_d[B_ * 4096];
__device__ float g_ah[B_ * R_];
__device__ float g_ac[B_ * R_];
__device__ float g_pq[B_ * A_];
__device__ float g_energies[B_ * T_];
__device__ float g_ctx[B_ * E_];
__device__ float g_dh[B_ * D_];
__device__ float g_dc[B_ * D_];

// ---------------- helpers ----------------
__device__ __forceinline__ unsigned f2tf(float f) {
    unsigned u;
    asm("cvt.rna.tf32.f32 %0, %1;" : "=r"(u) : "f"(f));
    return u;
}

__device__ __forceinline__ void mma_tf32(float* c,
    unsigned a0, unsigned a1, unsigned a2, unsigned a3,
    unsigned b0, unsigned b1)
{
    asm volatile(
        "mma.sync.aligned.m16n8k8.row.col.f32.tf32.tf32.f32 "
        "{%0,%1,%2,%3}, {%4,%5,%6,%7}, {%8,%9}, {%0,%1,%2,%3};"
        : "+f"(c[0]), "+f"(c[1]), "+f"(c[2]), "+f"(c[3])
        : "r"(a0), "r"(a1), "r"(a2), "r"(a3), "r"(b0), "r"(b1));
}

__device__ __forceinline__ void cp16(void* smem_dst, const void* gsrc) {
    unsigned dst = (unsigned)__cvta_generic_to_shared(smem_dst);
    asm volatile("cp.async.ca.shared.global [%0], [%1], 16;"
                 :: "r"(dst), "l"(gsrc));
}
__device__ __forceinline__ void cp_commit() {
    asm volatile("cp.async.commit_group;");
}
__device__ __forceinline__ void cp_wait1() {
    asm volatile("cp.async.wait_group 1;");
}
__device__ __forceinline__ void cp_wait0() {
    asm volatile("cp.async.wait_group 0;");
}

__device__ __forceinline__ float sigm(float x) { return 1.f / (1.f + __expf(-x)); }
__device__ __forceinline__ float fast_tanh(float x) {
    float e = __expf(2.f * x);
    return 1.f - __fdividef(2.f, e + 1.f);
}

// ---------------- output init: preload biases / zeros ----------------
__global__ void init_kernel(float* ga, const float* bia, const float* bha,
                            float* gd, const float* bid, const float* bhd,
                            float* pq, float* proj, const float* bp, float* ctx)
{
    int idx = blockIdx.x * blockDim.x + threadIdx.x;   // 0 .. 262143
    int n = idx & 4095;
    ga[idx] = bia[n] + bha[n];
    gd[idx] = bid[n] + bhd[n];
    if (idx < B_ * A_) pq[idx] = 0.f;
    if (idx < B_ * H_) proj[idx] = bp[idx & (H_ - 1)];
    if (idx < B_ * E_) ctx[idx] = 0.f;
}

// ---------------- tf32 MMA 3-segment GEMM, split-K + cp.async pipeline ----------
__global__ __launch_bounds__(128) void mma_gemm3(
    const float* __restrict__ x1, const float* __restrict__ W1, int K1, int ld1,
    const float* __restrict__ x2, const float* __restrict__ W2, int K2, int ld2,
    const float* __restrict__ x3, const float* __restrict__ W3, int K3, int ld3,
    float* __restrict__ C, int N)
{
    __shared__ float As[3][64][36];
    __shared__ float Ws[3][32][36];

    const int tid  = threadIdx.x;
    const int lane = tid & 31;
    const int w    = tid >> 5;
    const int gid  = lane >> 2;
    const int tig  = lane & 3;
    const int n0   = blockIdx.x * 32;

    const int S      = gridDim.y;
    const int nt_tot = (K1 + K2 + K3) >> 5;
    const int per    = (nt_tot + S - 1) / S;
    const int gt0    = blockIdx.y * per;
    const int gt1    = min(gt0 + per, nt_tot);

    float acc[4][4] = {};

    int base = 0;
#pragma unroll
    for (int s = 0; s < 3; s++) {
        const float* x  = (s == 0) ? x1 : (s == 1) ? x2 : x3;
        const float* W  = (s == 0) ? W1 : (s == 1) ? W2 : W3;
        const int K     = (s == 0) ? K1 : (s == 1) ? K2 : K3;
        const int ld    = (s == 0) ? ld1 : (s == 1) ? ld2 : ld3;
        if (K == 0) continue;
        const int nts = K >> 5;
        const int lo = max(gt0 - base, 0), hi = min(gt1 - base, nts);
        base += nts;
        if (lo >= hi) continue;

        __syncthreads();

        auto issue = [&](int tile, int buf) {
            int k0 = tile * 32;
#pragma unroll
            for (int r = 0; r < 4; r++) {
                int j = tid + r * 128;
                int m = j >> 3, kq = j & 7;
                cp16(&As[buf][m][kq * 4], x + (size_t)m * K + k0 + kq * 4);
            }
#pragma unroll
            for (int r = 0; r < 2; r++) {
                int j = tid + r * 128;
                int n = j >> 3, kq = j & 7;
                cp16(&Ws[buf][n][kq * 4], W + (size_t)(n0 + n) * ld + k0 + kq * 4);
            }
        };

        issue(lo, 0);
        cp_commit();
        if (hi - lo > 1) issue(lo + 1, 1);
        cp_commit();

        for (int it = lo; it < hi; it++) {
            cp_wait1();
            __syncthreads();
            int nx = it + 2;
            if (nx < hi) issue(nx, (nx - lo) % 3);
            cp_commit();

            const int buf = (it - lo) % 3;
#pragma unroll
            for (int kk = 0; kk < 32; kk += 8) {
                unsigned bb0 = f2tf(Ws[buf][w * 8 + gid][kk + tig]);
                unsigned bb1 = f2tf(Ws[buf][w * 8 + gid][kk + tig + 4]);
#pragma unroll
                for (int mt = 0; mt < 4; mt++) {
                    int ra = mt * 16 + gid;
                    unsigned a0 = f2tf(As[buf][ra][kk + tig]);
                    unsigned a1 = f2tf(As[buf][ra + 8][kk + tig]);
                    unsigned a2 = f2tf(As[buf][ra][kk + tig + 4]);
                    unsigned a3 = f2tf(As[buf][ra + 8][kk + tig + 4]);
                    mma_tf32(acc[mt], a0, a1, a2, a3, bb0, bb1);
                }
            }
        }
    }

    int n = n0 + w * 8 + tig * 2;
#pragma unroll
    for (int mt = 0; mt < 4; mt++) {
        int ra = mt * 16 + gid, rb = ra + 8;
        atomicAdd(&C[(size_t)ra * N + n],     acc[mt][0]);
        atomicAdd(&C[(size_t)ra * N + n + 1], acc[mt][1]);
        atomicAdd(&C[(size_t)rb * N + n],     acc[mt][2]);
        atomicAdd(&C[(size_t)rb * N + n + 1], acc[mt][3]);
    }
}

// ---------------- LSTM pointwise (float4 vectorized) ----------------
__global__ __launch_bounds__(256) void lstm_pointwise(
    const float* __restrict__ gates, const float* __restrict__ c_prev,
    float* __restrict__ h_out, float* __restrict__ c_out, int Nc)
{
    int idx4 = blockIdx.x * blockDim.x + threadIdx.x;
    if (idx4 >= (B_ * 1024) / 4) return;
    int b = idx4 / (Nc / 4), j4 = idx4 - b * (Nc / 4);
    const float4* g = (const float4*)(gates + (size_t)b * 4 * Nc);
    int q = Nc / 4;
    float4 gi4 = g[j4];
    float4 gf4 = g[q + j4];
    float4 gg4 = g[2 * q + j4];
    float4 go4 = g[3 * q + j4];
    float4 cp4 = ((const float4*)c_prev)[idx4];
    float4 h4, c4;
    { float c2 = sigm(gf4.x) * cp4.x + sigm(gi4.x) * fast_tanh(gg4.x);
      h4.x = sigm(go4.x) * fast_tanh(c2); c4.x = c2; }
    { float c2 = sigm(gf4.y) * cp4.y + sigm(gi4.y) * fast_tanh(gg4.y);
      h4.y = sigm(go4.y) * fast_tanh(c2); c4.y = c2; }
    { float c2 = sigm(gf4.z) * cp4.z + sigm(gi4.z) * fast_tanh(gg4.z);
      h4.z = sigm(go4.z) * fast_tanh(c2); c4.z = c2; }
    { float c2 = sigm(gf4.w) * cp4.w + sigm(gi4.w) * fast_tanh(gg4.w);
      h4.w = sigm(go4.w) * fast_tanh(c2); c4.w = c2; }
    ((float4*)h_out)[idx4] = h4;
    ((float4*)c_out)[idx4] = c4;
}

// ---------------- fused conv31 + MMA location-fc + energy (v3) ----------------
// grid (T/128, B), 256 threads (8 warps). Warp w owns t-rows [w*16, w*16+16).
// Phase 1: conv -> s_cv (warp-local rows). Phase 2: one m16-tile MMA vs all
// 128 a-cols. Phase 3: in-fragment tanh-reduce with pm read DIRECT from global
// (per-nt request = 8 rows x 32B = 8 full sectors), energies stored directly.
__global__ __launch_bounds__(256) void energy_kernel(
    const float* __restrict__ att_w, const float* __restrict__ att_w_cum,
    const float* __restrict__ pm,        // [B,T,A]
    const float* __restrict__ pq,        // [B,A]
    const float* __restrict__ W_loc,     // [F,2,31]
    const float* __restrict__ W_lfc,     // [A,F]
    const float* __restrict__ W_v,       // [A]
    float* __restrict__ energies)        // [B,T]
{
    __shared__ float s_lfc[128 * 36];
    __shared__ float s_cv[128 * 36];
    __shared__ float s_w[F_ * 2 * KS_];
    __shared__ float s_aw[2 * 158];
    __shared__ float s_pq[128];
    __shared__ float s_wv[128];

    const int b   = blockIdx.y;
    const int t0  = blockIdx.x * 128;
    const int tid = threadIdx.x;
    const int lane = tid & 31, w = tid >> 5;
    const int gid = lane >> 2, tig = lane & 3;

    // cp.async prefetch: lfc, pq, wv (land before phase 2/3)
#pragma unroll
    for (int r = 0; r < 4; r++) {
        int idx = tid + r * 256;
        int row = idx >> 3, q = idx & 7;
        cp16(s_lfc + row * 36 + q * 4, W_lfc + row * 32 + q * 4);
    }
    if (tid < 32)      cp16(s_pq + tid * 4, pq + b * A_ + tid * 4);
    else if (tid < 64) cp16(s_wv + (tid - 32) * 4, W_v + (tid - 32) * 4);
    cp_commit();

    // halo + conv weights (plain loads)
    for (int i = tid; i < 158; i += 256) {
        int g = t0 - PAD_ + i;
        bool ok = (g >= 0) && (g < T_);
        s_aw[i]       = ok ? att_w[b * T_ + g] : 0.f;
        s_aw[158 + i] = ok ? att_w_cum[b * T_ + g] : 0.f;
    }
    for (int i = tid; i < F_ * 2 * KS_; i += 256) s_w[i] = W_loc[i];
    __syncthreads();

    // phase 1: conv -> s_cv[t][f]; thread = (f = tid&31, tg = w), 16 t's
    {
        int f = tid & 31;
        float acc[16];
#pragma unroll
        for (int i = 0; i < 16; i++) acc[i] = 0.f;
#pragma unroll
        for (int c = 0; c < 2; c++) {
            float av[46];
#pragma unroll
            for (int i = 0; i < 46; i++) av[i] = s_aw[c * 158 + w * 16 + i];
#pragma unroll
            for (int k = 0; k < KS_; k++) {
                float wv = s_w[(f * 2 + c) * KS_ + k];
#pragma unroll
                for (int tt = 0; tt < 16; tt++) acc[tt] += wv * av[k + tt];
            }
        }
#pragma unroll
        for (int tt = 0; tt < 16; tt++) s_cv[(w * 16 + tt) * 36 + f] = acc[tt];
    }
    cp_wait0();
    __syncthreads();

    // phase 2: MMA la[w*16..+15][0..127] = cv @ lfc^T  (16 n-tiles, 4 k-steps)
    float acc[16][4];
#pragma unroll
    for (int nt = 0; nt < 16; nt++)
#pragma unroll
        for (int i = 0; i < 4; i++) acc[nt][i] = 0.f;

#pragma unroll
    for (int kk = 0; kk < 32; kk += 8) {
        int ra = w * 16 + gid;
        unsigned a0 = f2tf(s_cv[ra * 36 + kk + tig]);
        unsigned a1 = f2tf(s_cv[(ra + 8) * 36 + kk + tig]);
        unsigned a2 = f2tf(s_cv[ra * 36 + kk + tig + 4]);
        unsigned a3 = f2tf(s_cv[(ra + 8) * 36 + kk + tig + 4]);
#pragma unroll
        for (int nt = 0; nt < 16; nt++) {
            unsigned bb0 = f2tf(s_lfc[(nt * 8 + gid) * 36 + kk + tig]);
            unsigned bb1 = f2tf(s_lfc[(nt * 8 + gid) * 36 + kk + tig + 4]);
            mma_tf32(acc[nt], a0, a1, a2, a3, bb0, bb1);
        }
    }

    // phase 3: tanh-reduce in fragment layout; pm direct from global
    {
        int tg0 = t0 + w * 16 + gid;            // global t of fragment row 0
        const float* pm0 = pm + ((size_t)b * T_ + tg0) * A_;
        const float* pm1 = pm0 + 8 * A_;        // row +8
        float part0 = 0.f, part1 = 0.f;
#pragma unroll
        for (int nt = 0; nt < 16; nt++) {
            int a0 = nt * 8 + tig * 2;
            float pq0 = s_pq[a0], pq1 = s_pq[a0 + 1];
            float wv0 = s_wv[a0], wv1 = s_wv[a0 + 1];
            float2 p0 = *(const float2*)(pm0 + a0);
            float2 p1 = *(const float2*)(pm1 + a0);
            part0 += fast_tanh(pq0 + p0.x + acc[nt][0]) * wv0
                   + fast_tanh(pq1 + p0.y + acc[nt][1]) * wv1;
            part1 += fast_tanh(pq0 + p1.x + acc[nt][2]) * wv0
                   + fast_tanh(pq1 + p1.y + acc[nt][3]) * wv1;
        }
        // reduce over tig (lanes xor 1, xor 2)
        part0 += __shfl_xor_sync(0xffffffffu, part0, 1);
        part0 += __shfl_xor_sync(0xffffffffu, part0, 2);
        part1 += __shfl_xor_sync(0xffffffffu, part1, 1);
        part1 += __shfl_xor_sync(0xffffffffu, part1, 2);
        if (tig == 0) {
            energies[b * T_ + tg0]     = part0;
            energies[b * T_ + tg0 + 8] = part1;
        }
    }
}

// ---------------- masked softmax over T (mask int32) ----------------
__global__ __launch_bounds__(256) void softmax_kernel(
    const float* __restrict__ energies, const int* __restrict__ mask,
    float* __restrict__ weights)
{
    int b = blockIdx.x, tid = threadIdx.x;
    __shared__ float red[8];
    __shared__ float s_bcast;
    float v[8];
    float mx = -3.4e38f;
#pragma unroll
    for (int r = 0; r < 8; r++) {
        int t = tid + r * 256;
        float e = energies[b * T_ + t];
        if (mask[b * T_ + t] != 0) e = -1e30f;
        v[r] = e;
        mx = fmaxf(mx, e);
    }
#pragma unroll
    for (int o = 16; o; o >>= 1) mx = fmaxf(mx, __shfl_xor_sync(0xffffffffu, mx, o));
    if ((tid & 31) == 0) red[tid >> 5] = mx;
    __syncthreads();
    if (tid < 8) {
        float m = red[tid];
#pragma unroll
        for (int o = 4; o; o >>= 1) m = fmaxf(m, __shfl_xor_sync(0xffu, m, o));
        if (tid == 0) s_bcast = m;
    }
    __syncthreads();
    mx = s_bcast;
    float sum = 0.f;
#pragma unroll
    for (int r = 0; r < 8; r++) { v[r] = __expf(v[r] - mx); sum += v[r]; }
#pragma unroll
    for (int o = 16; o; o >>= 1) sum += __shfl_xor_sync(0xffffffffu, sum, o);
    if ((tid & 31) == 0) red[tid >> 5] = sum;
    __syncthreads();
    if (tid < 8) {
        float m = red[tid];
#pragma unroll
        for (int o = 4; o; o >>= 1) m += __shfl_xor_sync(0xffu, m, o);
        if (tid == 0) s_bcast = m;
    }
    __syncthreads();
    float inv = 1.f / s_bcast;
#pragma unroll
    for (int r = 0; r < 8; r++) weights[b * T_ + tid + r * 256] = v[r] * inv;
}

// ---------------- context (split-T, atomic; ctx pre-zeroed by init) ----------
__global__ __launch_bounds__(256) void ctx_kernel(
    const float* __restrict__ weights, const float* __restrict__ memory,
    float* __restrict__ ctx)
{
    int b = blockIdx.y;
    int t0 = blockIdx.x * 128;
    int e = threadIdx.x;
    const float* mb = memory + ((size_t)b * T_ + t0) * E_ + e;
    const float* wb = weights + b * T_ + t0;
    float acc = 0.f;
#pragma unroll 4
    for (int t = 0; t < 128; t++) acc += wb[t] * mb[(size_t)t * E_];
    atomicAdd(&ctx[b * E_ + e], acc);
}

// ---------------- stop gate ----------------
__global__ __launch_bounds__(1024) void gate_kernel(
    const float* __restrict__ dh, const float* __restrict__ ctx,
    const float* __restrict__ W_gate, const float* __restrict__ b_gate,
    float* __restrict__ out_stop)
{
    int gtid = blockIdx.x * 1024 + threadIdx.x;
    int r = gtid >> 5, lane = gtid & 31;
    float acc = 0.f;
    const float* xr = dh + (size_t)r * D_;
#pragma unroll 4
    for (int k = lane; k < D_; k += 32) acc += xr[k] * W_gate[k];
    const float* cr = ctx + (size_t)r * E_;
#pragma unroll 4
    for (int k = lane; k < E_; k += 32) acc += cr[k] * W_gate[D_ + k];
#pragma unroll
    for (int o = 16; o; o >>= 1) acc += __shfl_xor_sync(0xffffffffu, acc, o);
    if (lane == 0) out_stop[r] = acc + b_gate[0];
}

// ---------------- launch ----------------
extern "C" void kernel_launch(void* const* d_in, const int* in_sizes, int n_in,
                              void* d_out, int out_size)
{
    const float* last_frame = (const float*)d_in[0];
    const float* att_h      = (const float*)d_in[1];
    const float* att_c      = (const float*)d_in[2];
    const float* att_w      = (const float*)d_in[3];
    const float* att_w_cum  = (const float*)d_in[4];
    const float* att_ctx    = (const float*)d_in[5];
    const float* dec_h      = (const float*)d_in[6];
    const float* dec_c      = (const float*)d_in[7];
    const float* memory     = (const float*)d_in[8];
    const float* pmem       = (const float*)d_in[9];
    const float* W_ih_a     = (const float*)d_in[10];
    const float* W_hh_a     = (const float*)d_in[11];
    const float* b_ih_a     = (const float*)d_in[12];
    const float* b_hh_a     = (const float*)d_in[13];
    const float* W_q        = (const float*)d_in[14];
    const float* W_v        = (const float*)d_in[15];
    const float* W_loc      = (const float*)d_in[16];
    const float* W_lfc      = (const float*)d_in[17];
    const float* W_ih_d     = (const float*)d_in[18];
    const float* W_hh_d     = (const float*)d_in[19];
    const float* b_ih_d     = (const float*)d_in[20];
    const float* b_hh_d     = (const float*)d_in[21];
    const float* W_proj     = (const float*)d_in[22];
    const float* b_proj     = (const float*)d_in[23];
    const float* W_gate     = (const float*)d_in[24];
    const float* b_gate     = (const float*)d_in[25];
    const int*   mask       = (const int*)d_in[26];

    float* out = (float*)d_out;
    float* out_proj = out;                      // [64,256]
    float* out_stop = out + B_ * H_;            // [64,1]
    float* out_w    = out + B_ * H_ + B_;       // [64,2048]

    float *gates_a, *gates_d, *ah, *ac, *pq, *energies, *ctx, *dh, *dc;
    cudaGetSymbolAddress((void**)&gates_a,  g_gates_a);
    cudaGetSymbolAddress((void**)&gates_d,  g_gates_d);
    cudaGetSymbolAddress((void**)&ah,       g_ah);
    cudaGetSymbolAddress((void**)&ac,       g_ac);
    cudaGetSymbolAddress((void**)&pq,       g_pq);
    cudaGetSymbolAddress((void**)&energies, g_energies);
    cudaGetSymbolAddress((void**)&ctx,      g_ctx);
    cudaGetSymbolAddress((void**)&dh,       g_dh);
    cudaGetSymbolAddress((void**)&dc,       g_dc);

    // 0) init outputs with biases / zeros
    init_kernel<<<1024, 256>>>(gates_a, b_ih_a, b_hh_a,
                               gates_d, b_ih_d, b_hh_d,
                               pq, out_proj, b_proj, ctx);

    // 1) attention LSTM gates (split-K 8)
    mma_gemm3<<<dim3(128, 8), 128>>>(last_frame, W_ih_a,       P_, P_ + E_,
                                     att_ctx,    W_ih_a + P_,  E_, P_ + E_,
                                     att_h,      W_hh_a,       R_, R_,
                                     gates_a, 4 * R_);
    lstm_pointwise<<<(B_ * R_) / 1024, 256>>>(gates_a, att_c, ah, ac, R_);

    // 2) query projection pq = ah @ W_q^T (split-K 8)
    mma_gemm3<<<dim3(A_ / 32, 8), 128>>>(ah, W_q, R_, R_,
                                         nullptr, nullptr, 0, 0,
                                         nullptr, nullptr, 0, 0,
                                         pq, A_);

    // 3) fused conv + MMA-la + energies (v3), then softmax
    energy_kernel<<<dim3(T_ / 128, B_), 256>>>(
        att_w, att_w_cum, pmem, pq, W_loc, W_lfc, W_v, energies);
    softmax_kernel<<<B_, 256>>>(energies, mask, out_w);

    // 4) context
    ctx_kernel<<<dim3(16, B_), 256>>>(out_w, memory, ctx);

    // 5) decoder LSTM gates (split-K 16)
    mma_gemm3<<<dim3(128, 16), 128>>>(ah,    W_ih_d,       R_, R_ + E_,
                                      ctx,   W_ih_d + R_,  E_, R_ + E_,
                                      dec_h, W_hh_d,       D_, D_,
                                      gates_d, 4 * D_);
    lstm_pointwise<<<(B_ * D_) / 1024, 256>>>(gates_d, dec_c, dh, dc, D_);

    // 6) output heads (proj split-K 8)
    mma_gemm3<<<dim3(H_ / 32, 8), 128>>>(dh,  W_proj,       D_, D_ + E_,
                                         ctx, W_proj + D_,  E_, D_ + E_,
                                         nullptr, nullptr, 0, 0,
                                         out_proj, H_);
    gate_kernel<<<2, 1024>>>(dh, ctx, W_gate, b_gate, out_stop);
}